// round 2
// baseline (speedup 1.0000x reference)
#include <cuda_runtime.h>
#include <math.h>

// QLinear with expquantize(n=2) weights:
//   wq nonzero  <=>  |w| >= 2^-2.5  (an 8.8-sigma event for N(0, 0.02^2) data)
// Fast path: per-row survivor flags + bias quantization + broadcast fill.
// Slow path (k_fixup) handles any column whose weight row actually survives,
// so the kernel is correct for arbitrary inputs, not just the benchmark seed.

#define MAX_OUT 4096
#define MAX_IN  4096

__device__ float g_bq[MAX_OUT];
__device__ int   g_flag[MAX_OUT];

// Exact match of the reference expquantize:
//   y = sign(x) * exp2(round(log2(|clip(x,-1,1)|)));  y = 0 if |y| < 0.25
// rintf = round-half-to-even, matching jnp.round. log2f(0) = -inf -> exp2f -> 0.
__device__ __forceinline__ float expquantize_exact(float x) {
    float c = fminf(fmaxf(x, -1.0f), 1.0f);
    float a = fabsf(c);
    float y = (a > 0.0f) ? exp2f(rintf(log2f(a))) : 0.0f;
    y = copysignf(y, x);
    if (fabsf(y) < 0.25f) y = 0.0f;
    return y;
}

// ---------------------------------------------------------------------------
// Kernel 1: per-OUT-row survivor flag (cheap FP compare, no MUFU) + bias quant.
// Survivor condition |w| >= 2^-2.5; the clamp to [-1,1] cannot change the
// compare since the threshold < 1.
// ---------------------------------------------------------------------------
__global__ void k_meta(const float* __restrict__ w,
                       const float* __restrict__ bias,
                       int IN, int OUT) {
    int j = blockIdx.x;
    if (j >= OUT) return;

    const float4* w4 = reinterpret_cast<const float4*>(w + (size_t)j * IN);
    const int n4 = IN >> 2;
    const float T = 0.17677669529663687f;  // 2^-2.5

    int nz = 0;
    for (int k = threadIdx.x; k < n4; k += blockDim.x) {
        float4 v = __ldg(&w4[k]);
        nz |= (fabsf(v.x) >= T);
        nz |= (fabsf(v.y) >= T);
        nz |= (fabsf(v.z) >= T);
        nz |= (fabsf(v.w) >= T);
    }
    int any = __syncthreads_or(nz);
    if (threadIdx.x == 0) {
        g_flag[j] = any;
        g_bq[j]   = expquantize_exact(bias[j]);
    }
}

// ---------------------------------------------------------------------------
// Kernel 2: out[i, :] = bq[:]  (float4, fully coalesced; bq stays in L1/L2).
// Columns whose weight row survived get overwritten by k_fixup afterwards.
// ---------------------------------------------------------------------------
__global__ void k_fill(float* __restrict__ out, int OUT, int B) {
    const int n4 = OUT >> 2;
    int j4 = blockIdx.x * blockDim.x + threadIdx.x;
    if (j4 >= n4) return;

    float4 b = reinterpret_cast<const float4*>(g_bq)[j4];
    float4* out4 = reinterpret_cast<float4*>(out);
    for (int i = blockIdx.y; i < B; i += gridDim.y) {
        out4[(size_t)i * n4 + j4] = b;
    }
}

// ---------------------------------------------------------------------------
// Kernel 3: rare path. One block per output column; exits immediately unless
// that weight row has a quantization survivor. Correctness insurance only.
// ---------------------------------------------------------------------------
__global__ void k_fixup(const float* __restrict__ x,
                        const float* __restrict__ w,
                        float* __restrict__ out,
                        int B, int IN, int OUT) {
    int j = blockIdx.x;
    if (j >= OUT) return;
    if (!g_flag[j]) return;

    __shared__ float wq_s[MAX_IN];
    for (int k = threadIdx.x; k < IN; k += blockDim.x)
        wq_s[k] = expquantize_exact(w[(size_t)j * IN + k]);
    __syncthreads();

    float bqj = g_bq[j];
    for (int i = threadIdx.x; i < B; i += blockDim.x) {
        const float* xr = x + (size_t)i * IN;
        float acc = 0.0f;
        #pragma unroll 4
        for (int k = 0; k < IN; ++k)
            acc = fmaf(xr[k], wq_s[k], acc);
        out[(size_t)i * OUT + j] = acc + bqj;
    }
}

extern "C" void kernel_launch(void* const* d_in, const int* in_sizes, int n_in,
                              void* d_out, int out_size) {
    const float* x    = (const float*)d_in[0];
    const float* w    = (const float*)d_in[1];
    const float* bias = (const float*)d_in[2];
    float* out = (float*)d_out;

    const int OUT = in_sizes[2];            // 4096
    const int IN  = in_sizes[1] / OUT;      // 4096
    const int B   = in_sizes[0] / IN;       // 8192

    // 1) flags + quantized bias (reads all of weight once)
    k_meta<<<OUT, 256>>>(w, bias, IN, OUT);

    // 2) broadcast bias into the output (dominant cost: 128 MB of stores)
    const int n4 = OUT >> 2;
    dim3 fill_grid((n4 + 255) / 256, 2048);
    k_fill<<<fill_grid, 256>>>(out, OUT, B);

    // 3) exact recompute for any column with surviving weights (normally no-op)
    k_fixup<<<OUT, 256>>>(x, w, out, B, IN, OUT);
}

// round 3
// speedup vs baseline: 1.0497x; 1.0497x over previous
#include <cuda_runtime.h>
#include <math.h>

// QLinear with expquantize(n=2): a weight/bias survives quantization iff
// |v| >= 2^-2.5 (8.8-sigma for N(0,0.02^2) data -> never, for the bench data).
// Fused fast path: one kernel where 1/3 of blocks scan weight rows for
// survivors (64 MB reads) while 2/3 broadcast quantized bias into the output
// (128 MB writes) -- reads and writes overlap on HBM instead of serializing.
// k_fixup then exactly recomputes any column whose weight row survived
// (no-op for the bench data), keeping the kernel correct for arbitrary inputs.

#define MAX_OUT 4096
#define T_SURV 0.17677669529663687f   // 2^-2.5

__device__ int g_flag[MAX_OUT];

// expquantize with compare-first fast path: the MUFU ops (log2f/exp2f) are
// predicated off unless the value actually survives quantization.
// rintf = round-half-to-even, matching jnp.round.
__device__ __forceinline__ float expquantize_exact(float x) {
    float a = fabsf(x);
    if (a < T_SURV) return 0.0f;          // below lb (and zero) -> 0
    a = fminf(a, 1.0f);                   // clamp (|x|>1 case)
    float y = exp2f(rintf(log2f(a)));
    if (y < 0.25f) y = 0.0f;              // boundary safety
    return copysignf(y, x);
}

// ---------------------------------------------------------------------------
// Fused kernel. bid % 3 == 0 -> weight scan (SCAN_BLOCKS total);
// otherwise -> output fill (FILL_BLOCKS total). Interleaving keeps a
// read/write mix resident on every SM.
// ---------------------------------------------------------------------------
__global__ void k_fused(const float* __restrict__ w,
                        const float* __restrict__ bias,
                        float* __restrict__ out,
                        int IN, int OUT, int B,
                        int SCAN_BLOCKS, int FILL_BLOCKS) {
    const int bid = blockIdx.x;
    const int tid = threadIdx.x;

    if (bid % 3 == 0) {
        // ----- weight scan: per-row "any survivor" flag -----
        const int sid = bid / 3;                 // 0 .. SCAN_BLOCKS-1
        const int n4 = IN >> 2;
        for (int j = sid; j < OUT; j += SCAN_BLOCKS) {
            const float4* w4 = reinterpret_cast<const float4*>(w + (size_t)j * IN);
            int nz = 0;
            #pragma unroll 4
            for (int k = tid; k < n4; k += 256) {
                float4 v = __ldcs(&w4[k]);       // streaming read, never reused
                nz |= (fabsf(v.x) >= T_SURV);
                nz |= (fabsf(v.y) >= T_SURV);
                nz |= (fabsf(v.z) >= T_SURV);
                nz |= (fabsf(v.w) >= T_SURV);
            }
            int any = __syncthreads_or(nz);
            if (tid == 0) g_flag[j] = any;
        }
    } else {
        // ----- output fill: out[i, :] = expquantize(bias)[:] -----
        const int fid = bid - bid / 3 - 1;       // 0 .. FILL_BLOCKS-1
        const int n4 = OUT >> 2;
        const int num_jblk = n4 >> 8;            // n4 / 256 (=4 for OUT=4096)
        const int jblk = fid % num_jblk;
        const int y0   = fid / num_jblk;
        const int ystr = FILL_BLOCKS / num_jblk;

        const int j4 = jblk * 256 + tid;
        if (j4 < n4) {
            const int j = j4 * 4;
            float4 b;
            b.x = expquantize_exact(bias[j + 0]);   // MUFU predicated off in
            b.y = expquantize_exact(bias[j + 1]);   // practice; computed once,
            b.z = expquantize_exact(bias[j + 2]);   // reused for every row
            b.w = expquantize_exact(bias[j + 3]);

            float4* out4 = reinterpret_cast<float4*>(out);
            for (int i = y0; i < B; i += ystr) {
                __stcs(&out4[(size_t)i * n4 + j4], b);  // streaming store
            }
        }
    }
}

// ---------------------------------------------------------------------------
// Rare path: one block per output column, early-exit unless flagged.
// ---------------------------------------------------------------------------
__global__ void k_fixup(const float* __restrict__ x,
                        const float* __restrict__ w,
                        const float* __restrict__ bias,
                        float* __restrict__ out,
                        int B, int IN, int OUT) {
    const int j = blockIdx.x;
    if (j >= OUT) return;
    if (!g_flag[j]) return;

    extern __shared__ float wq_s[];
    for (int k = threadIdx.x; k < IN; k += blockDim.x)
        wq_s[k] = expquantize_exact(w[(size_t)j * IN + k]);
    __syncthreads();

    const float bqj = expquantize_exact(bias[j]);
    for (int i = threadIdx.x; i < B; i += blockDim.x) {
        const float* xr = x + (size_t)i * IN;
        float acc = 0.0f;
        #pragma unroll 4
        for (int k = 0; k < IN; ++k)
            acc = fmaf(xr[k], wq_s[k], acc);
        out[(size_t)i * OUT + j] = acc + bqj;
    }
}

extern "C" void kernel_launch(void* const* d_in, const int* in_sizes, int n_in,
                              void* d_out, int out_size) {
    const float* x    = (const float*)d_in[0];
    const float* w    = (const float*)d_in[1];
    const float* bias = (const float*)d_in[2];
    float* out = (float*)d_out;

    const int OUT = in_sizes[2];            // 4096
    const int IN  = in_sizes[1] / OUT;      // 4096
    const int B   = in_sizes[0] / IN;       // 8192

    // 1 scan block : 2 fill blocks (64 MB reads : 128 MB writes)
    const int SCAN_BLOCKS = 1024;
    const int FILL_BLOCKS = 2048;
    const int TOTAL = SCAN_BLOCKS + FILL_BLOCKS;   // 3072, bid%3 split

    k_fused<<<TOTAL, 256>>>(w, bias, out, IN, OUT, B, SCAN_BLOCKS, FILL_BLOCKS);

    // exact recompute for any surviving column (normally all blocks early-exit)
    k_fixup<<<OUT, 128, IN * sizeof(float)>>>(x, w, bias, out, B, IN, OUT);
}

// round 4
// speedup vs baseline: 1.0848x; 1.0334x over previous
#include <cuda_runtime.h>
#include <math.h>

// QLinear with expquantize(n=2): a value survives quantization iff
// |v| >= 2^-2.5 (8.8-sigma for N(0,0.02^2) data -> never, for the bench data).
// Fast path: one fused kernel (1/3 blocks scan weights for survivors, 2/3
// broadcast quantized bias into the output). A tiny 256-block guard kernel
// exactly recomputes any column whose weight row survived (no-op normally),
// keeping the kernel correct for arbitrary inputs.

#define MAX_OUT 4096
#define T_SURV 0.17677669529663687f   // 2^-2.5

__device__ int g_flag[MAX_OUT];

// expquantize, compare-first so MUFU (log2f/exp2f) is predicated off unless
// the value actually survives. rintf = round-half-to-even = jnp.round.
__device__ __forceinline__ float expquantize_exact(float x) {
    float a = fabsf(x);
    if (a < T_SURV) return 0.0f;
    a = fminf(a, 1.0f);
    float y = exp2f(rintf(log2f(a)));
    if (y < 0.25f) y = 0.0f;
    return copysignf(y, x);
}

// ---------------------------------------------------------------------------
// Fused kernel. bid % 3 == 0 -> weight scan; else -> output fill.
// Scan blocks process TWO rows at once: 8 independent float4 loads in flight
// per thread per unrolled pass (2x the MLP of the one-row version).
// ---------------------------------------------------------------------------
__global__ void __launch_bounds__(256) k_fused(
        const float* __restrict__ w,
        const float* __restrict__ bias,
        float* __restrict__ out,
        int IN, int OUT, int B,
        int SCAN_BLOCKS, int FILL_BLOCKS) {
    const int bid = blockIdx.x;
    const int tid = threadIdx.x;

    if (bid % 3 == 0) {
        // ----- weight scan: per-row "any survivor" flags, 2 rows per pass ---
        const int sid = bid / 3;                   // 0 .. SCAN_BLOCKS-1
        const int n4 = IN >> 2;                    // 1024
        const int npairs = OUT >> 1;               // 2048
        const float4* w4 = reinterpret_cast<const float4*>(w);

        for (int p = sid; p < npairs; p += SCAN_BLOCKS) {
            const float4* r0 = w4 + (size_t)(2 * p) * n4;
            const float4* r1 = r0 + n4;
            int nz = 0;
            #pragma unroll 4
            for (int k = tid; k < n4; k += 256) {  // 4 iters -> 8 loads batched
                float4 a = __ldcs(&r0[k]);
                float4 b = __ldcs(&r1[k]);
                nz |= (fabsf(a.x) >= T_SURV) | (fabsf(a.y) >= T_SURV)
                    | (fabsf(a.z) >= T_SURV) | (fabsf(a.w) >= T_SURV);
                nz |= ((fabsf(b.x) >= T_SURV) | (fabsf(b.y) >= T_SURV)
                    |  (fabsf(b.z) >= T_SURV) | (fabsf(b.w) >= T_SURV)) << 1;
            }
            int any = __syncthreads_or(nz);        // bit0 = row 2p, bit1 = 2p+1
            if (tid == 0) {
                g_flag[2 * p]     = any & 1;
                g_flag[2 * p + 1] = (any >> 1) & 1;
            }
        }
    } else {
        // ----- output fill: out[i, :] = expquantize(bias)[:] ----------------
        const int fid = bid - bid / 3 - 1;         // 0 .. FILL_BLOCKS-1
        const int n4 = OUT >> 2;
        const int num_jblk = n4 >> 8;              // 4 for OUT=4096
        const int jblk = fid % num_jblk;
        const int y0   = fid / num_jblk;
        const int ystr = FILL_BLOCKS / num_jblk;

        const int j4 = jblk * 256 + tid;
        if (j4 < n4) {
            const int j = j4 * 4;
            float4 b;
            b.x = expquantize_exact(bias[j + 0]);
            b.y = expquantize_exact(bias[j + 1]);
            b.z = expquantize_exact(bias[j + 2]);
            b.w = expquantize_exact(bias[j + 3]);

            float4* out4 = reinterpret_cast<float4*>(out);
            for (int i = y0; i < B; i += ystr)
                __stcs(&out4[(size_t)i * n4 + j4], b);
        }
    }
}

// ---------------------------------------------------------------------------
// Guard + rare path: 256 blocks; block b or-reduces 16 flags (L2-hot) and
// exits. Only if a flag in its range is set does it recompute those columns.
// ---------------------------------------------------------------------------
__global__ void __launch_bounds__(256) k_fixup(
        const float* __restrict__ x,
        const float* __restrict__ w,
        const float* __restrict__ bias,
        float* __restrict__ out,
        int B, int IN, int OUT) {
    const int per = OUT >> 8;                       // 16 columns per block
    const int j0 = blockIdx.x * per;

    // cheap guard: 16 flag loads by the first 16 threads, one ballot
    int mine = (threadIdx.x < per) ? g_flag[j0 + threadIdx.x] : 0;
    int any = __syncthreads_or(mine);
    if (!any) return;

    extern __shared__ float wq_s[];
    for (int jj = 0; jj < per; ++jj) {
        const int j = j0 + jj;
        if (!g_flag[j]) continue;

        for (int k = threadIdx.x; k < IN; k += blockDim.x)
            wq_s[k] = expquantize_exact(w[(size_t)j * IN + k]);
        __syncthreads();

        const float bqj = expquantize_exact(bias[j]);
        for (int i = threadIdx.x; i < B; i += blockDim.x) {
            const float* xr = x + (size_t)i * IN;
            float acc = 0.0f;
            #pragma unroll 4
            for (int k = 0; k < IN; ++k)
                acc = fmaf(xr[k], wq_s[k], acc);
            out[(size_t)i * OUT + j] = acc + bqj;
        }
        __syncthreads();
    }
}

extern "C" void kernel_launch(void* const* d_in, const int* in_sizes, int n_in,
                              void* d_out, int out_size) {
    const float* x    = (const float*)d_in[0];
    const float* w    = (const float*)d_in[1];
    const float* bias = (const float*)d_in[2];
    float* out = (float*)d_out;

    const int OUT = in_sizes[2];            // 4096
    const int IN  = in_sizes[1] / OUT;      // 4096
    const int B   = in_sizes[0] / IN;       // 8192

    const int SCAN_BLOCKS = 1024;
    const int FILL_BLOCKS = 2048;
    const int TOTAL = SCAN_BLOCKS + FILL_BLOCKS;   // 3072, bid%3 split

    k_fused<<<TOTAL, 256>>>(w, bias, out, IN, OUT, B, SCAN_BLOCKS, FILL_BLOCKS);
    k_fixup<<<256, 256, IN * (int)sizeof(float)>>>(x, w, bias, out, B, IN, OUT);
}